// round 2
// baseline (speedup 1.0000x reference)
#include <cuda_runtime.h>
#include <math.h>
#include <stdint.h>

#define DD   768
#define NH   12
#define HD   64
#define NB   8
#define LL   1024
#define NEGV (-1000000.0f)

// ---------------- scratch (device globals; no cudaMalloc allowed) -------------
__device__ float g_Q[NB * LL * DD];
__device__ float g_K[NB * LL * DD];
__device__ float g_V[NB * LL * DD];
__device__ float g_S[(size_t)NB * NH * LL * LL];   // 402 MB scores/attn
__device__ float g_attn[NB * LL * DD];
__device__ float g_mha[NB * LL * DD];
__device__ float g_h1[NB * LL * DD];
__device__ float g_x[NB * LL * DD];
__device__ int   g_vl[2][NB];

// ---------------- mask valid-length counts ------------------------------------
__global__ void count_masks_kernel(const int* __restrict__ m1,
                                   const int* __restrict__ m2) {
    const int* m = (blockIdx.y == 0) ? m1 : m2;
    int b = blockIdx.x;
    int t = threadIdx.x;
    __shared__ int red[256];
    int cnt = 0;
    for (int i = t; i < LL; i += 256) cnt += (m[b * LL + i] != 0);
    red[t] = cnt;
    __syncthreads();
    for (int s = 128; s > 0; s >>= 1) {
        if (t < s) red[t] += red[t + s];
        __syncthreads();
    }
    if (t == 0) g_vl[blockIdx.y][b] = red[0];
}

// ---------------- generic NN SGEMM: C[M,N] = A[M,K] @ B[K,N] ------------------
// 128x128 tile, BK=8, 256 threads, 8x8 per-thread micro-tile.
// flags: 1=+bias[col], 2=relu, 4=+resid[r*N+c]
__global__ void __launch_bounds__(256)
sgemm_nn_kernel(const float* __restrict__ A, const float* __restrict__ Bm,
                const float* __restrict__ bias, const float* __restrict__ resid,
                float* __restrict__ C, int M, int N, int K, int flags) {
    __shared__ float As[8][128];
    __shared__ float Bs[8][128];
    const int t  = threadIdx.x;
    const int bm = blockIdx.y * 128;
    const int bn = blockIdx.x * 128;
    const int tr = t >> 4;   // 0..15
    const int tc = t & 15;   // 0..15

    float acc[8][8];
#pragma unroll
    for (int i = 0; i < 8; ++i)
#pragma unroll
        for (int j = 0; j < 8; ++j) acc[i][j] = 0.0f;

    const int arow = t >> 1, ac4 = t & 1;     // A tile: 128 rows x 8 cols
    const int brow = t >> 5, bc4 = t & 31;    // B tile: 8 rows x 128 cols

    for (int k0 = 0; k0 < K; k0 += 8) {
        float4 va = *(const float4*)&A[(size_t)(bm + arow) * K + k0 + ac4 * 4];
        As[ac4 * 4 + 0][arow] = va.x;
        As[ac4 * 4 + 1][arow] = va.y;
        As[ac4 * 4 + 2][arow] = va.z;
        As[ac4 * 4 + 3][arow] = va.w;
        float4 vb = *(const float4*)&Bm[(size_t)(k0 + brow) * N + bn + bc4 * 4];
        *(float4*)&Bs[brow][bc4 * 4] = vb;
        __syncthreads();
#pragma unroll
        for (int k = 0; k < 8; ++k) {
            float a[8], bv[8];
            *(float4*)&a[0]  = *(const float4*)&As[k][tr * 8];
            *(float4*)&a[4]  = *(const float4*)&As[k][tr * 8 + 4];
            *(float4*)&bv[0] = *(const float4*)&Bs[k][tc * 8];
            *(float4*)&bv[4] = *(const float4*)&Bs[k][tc * 8 + 4];
#pragma unroll
            for (int i = 0; i < 8; ++i)
#pragma unroll
                for (int j = 0; j < 8; ++j) acc[i][j] += a[i] * bv[j];
        }
        __syncthreads();
    }

#pragma unroll
    for (int i = 0; i < 8; ++i) {
        int r = bm + tr * 8 + i;
#pragma unroll
        for (int j = 0; j < 8; ++j) {
            int c = bn + tc * 8 + j;
            float v = acc[i][j];
            if (flags & 1) v += bias[c];
            if (flags & 2) v = fmaxf(v, 0.0f);
            if (flags & 4) v += resid[(size_t)r * N + c];
            C[(size_t)r * N + c] = v;
        }
    }
}

// ---------------- batched scores: S[bh,i,j] = (Qh[i,:] . Kh[j,:]) / 8, masked --
__global__ void __launch_bounds__(256)
scores_kernel(const float* __restrict__ Q, const float* __restrict__ Kk,
              float* __restrict__ S) {
    const int bh = blockIdx.z;
    const int b  = bh / NH;
    const int h  = bh % NH;
    const float* A  = Q  + (size_t)b * LL * DD + h * HD;
    const float* Bm = Kk + (size_t)b * LL * DD + h * HD;
    float* C = S + (size_t)bh * LL * LL;

    __shared__ float As[8][128];
    __shared__ float Bs[8][128];
    const int t  = threadIdx.x;
    const int bm = blockIdx.y * 128;   // query rows
    const int bn = blockIdx.x * 128;   // key rows
    const int tr = t >> 4;
    const int tc = t & 15;

    float acc[8][8];
#pragma unroll
    for (int i = 0; i < 8; ++i)
#pragma unroll
        for (int j = 0; j < 8; ++j) acc[i][j] = 0.0f;

    const int row = t >> 1, c4 = t & 1;   // both tiles: 128 rows x 8 cols (of hd)

    for (int k0 = 0; k0 < HD; k0 += 8) {
        float4 va = *(const float4*)&A[(size_t)(bm + row) * DD + k0 + c4 * 4];
        As[c4 * 4 + 0][row] = va.x;
        As[c4 * 4 + 1][row] = va.y;
        As[c4 * 4 + 2][row] = va.z;
        As[c4 * 4 + 3][row] = va.w;
        float4 vb = *(const float4*)&Bm[(size_t)(bn + row) * DD + k0 + c4 * 4];
        Bs[c4 * 4 + 0][row] = vb.x;
        Bs[c4 * 4 + 1][row] = vb.y;
        Bs[c4 * 4 + 2][row] = vb.z;
        Bs[c4 * 4 + 3][row] = vb.w;
        __syncthreads();
#pragma unroll
        for (int k = 0; k < 8; ++k) {
            float a[8], bv[8];
            *(float4*)&a[0]  = *(const float4*)&As[k][tr * 8];
            *(float4*)&a[4]  = *(const float4*)&As[k][tr * 8 + 4];
            *(float4*)&bv[0] = *(const float4*)&Bs[k][tc * 8];
            *(float4*)&bv[4] = *(const float4*)&Bs[k][tc * 8 + 4];
#pragma unroll
            for (int i = 0; i < 8; ++i)
#pragma unroll
                for (int j = 0; j < 8; ++j) acc[i][j] += a[i] * bv[j];
        }
        __syncthreads();
    }

    const int vl1 = g_vl[0][b];   // key-axis valid length
    const int vl2 = g_vl[1][b];   // query-axis valid length
#pragma unroll
    for (int i = 0; i < 8; ++i) {
        int r = bm + tr * 8 + i;
        bool rok = r < vl2;
#pragma unroll
        for (int j = 0; j < 8; ++j) {
            int c = bn + tc * 8 + j;
            float v = acc[i][j] * 0.125f;
            C[(size_t)r * LL + c] = (rok && c < vl1) ? v : NEGV;
        }
    }
}

// ---------------- row softmax over 1024 ---------------------------------------
__global__ void __launch_bounds__(256) softmax_kernel(float* __restrict__ S) {
    const size_t row = blockIdx.x;
    float* p = S + row * LL;
    const int t = threadIdx.x;
    __shared__ float red[256];
    __shared__ float bcast;

    float4 v = *(const float4*)&p[t * 4];
    float m = fmaxf(fmaxf(v.x, v.y), fmaxf(v.z, v.w));
    red[t] = m;
    __syncthreads();
    for (int s = 128; s > 0; s >>= 1) {
        if (t < s) red[t] = fmaxf(red[t], red[t + s]);
        __syncthreads();
    }
    if (t == 0) bcast = red[0];
    __syncthreads();
    float mx = bcast;

    float4 e;
    e.x = __expf(v.x - mx);
    e.y = __expf(v.y - mx);
    e.z = __expf(v.z - mx);
    e.w = __expf(v.w - mx);
    red[t] = e.x + e.y + e.z + e.w;
    __syncthreads();
    for (int s = 128; s > 0; s >>= 1) {
        if (t < s) red[t] += red[t + s];
        __syncthreads();
    }
    if (t == 0) bcast = red[0];
    __syncthreads();
    float inv = 1.0f / bcast;

    e.x *= inv; e.y *= inv; e.z *= inv; e.w *= inv;
    *(float4*)&p[t * 4] = e;
}

// ---------------- batched PV: O[bh] = P[1024,1024] @ Vh[1024,64] --------------
// 128x64 tile, BK=16, 256 threads, 8x4 per-thread.
__global__ void __launch_bounds__(256)
pv_kernel(const float* __restrict__ S, const float* __restrict__ V,
          float* __restrict__ O) {
    const int bh = blockIdx.z;
    const int b  = bh / NH;
    const int h  = bh % NH;
    const float* A  = S + (size_t)bh * LL * LL;
    const float* Bm = V + (size_t)b * LL * DD + h * HD;
    float* C = O + (size_t)b * LL * DD + h * HD;

    __shared__ float As[16][128];
    __shared__ float Bs[16][64];
    const int t  = threadIdx.x;
    const int bm = blockIdx.y * 128;
    const int tr = t >> 4;   // 0..15 -> 8 rows each
    const int tc = t & 15;   // 0..15 -> 4 cols each

    float acc[8][4];
#pragma unroll
    for (int i = 0; i < 8; ++i)
#pragma unroll
        for (int j = 0; j < 4; ++j) acc[i][j] = 0.0f;

    const int brow = t >> 4, bc4 = t & 15;  // B tile: 16 rows x 64 cols

    for (int k0 = 0; k0 < LL; k0 += 16) {
        // A tile: 128 rows x 16 cols = 512 float4, 2 per thread
#pragma unroll
        for (int g = 0; g < 2; ++g) {
            int gi  = t * 2 + g;
            int row = gi >> 2, c4 = gi & 3;
            float4 va = *(const float4*)&A[(size_t)(bm + row) * LL + k0 + c4 * 4];
            As[c4 * 4 + 0][row] = va.x;
            As[c4 * 4 + 1][row] = va.y;
            As[c4 * 4 + 2][row] = va.z;
            As[c4 * 4 + 3][row] = va.w;
        }
        float4 vb = *(const float4*)&Bm[(size_t)(k0 + brow) * DD + bc4 * 4];
        *(float4*)&Bs[brow][bc4 * 4] = vb;
        __syncthreads();
#pragma unroll
        for (int k = 0; k < 16; ++k) {
            float a[8], bv[4];
            *(float4*)&a[0]  = *(const float4*)&As[k][tr * 8];
            *(float4*)&a[4]  = *(const float4*)&As[k][tr * 8 + 4];
            *(float4*)&bv[0] = *(const float4*)&Bs[k][tc * 4];
#pragma unroll
            for (int i = 0; i < 8; ++i)
#pragma unroll
                for (int j = 0; j < 4; ++j) acc[i][j] += a[i] * bv[j];
        }
        __syncthreads();
    }

#pragma unroll
    for (int i = 0; i < 8; ++i) {
        int r = bm + tr * 8 + i;
#pragma unroll
        for (int j = 0; j < 4; ++j)
            C[(size_t)r * DD + tc * 4 + j] = acc[i][j];
    }
}

// ---------------- layernorm over D=768 ----------------------------------------
__global__ void __launch_bounds__(256)
ln_kernel(const float* __restrict__ X, const float* __restrict__ gam,
          const float* __restrict__ bet, float* __restrict__ out) {
    const size_t row = blockIdx.x;
    const float* x = X + row * DD;
    const int t = threadIdx.x;
    __shared__ float red[256];
    __shared__ float bcast;

    float v0 = x[t], v1 = x[t + 256], v2 = x[t + 512];
    red[t] = v0 + v1 + v2;
    __syncthreads();
    for (int s = 128; s > 0; s >>= 1) {
        if (t < s) red[t] += red[t + s];
        __syncthreads();
    }
    if (t == 0) bcast = red[0] * (1.0f / DD);
    __syncthreads();
    float mu = bcast;

    float d0 = v0 - mu, d1 = v1 - mu, d2 = v2 - mu;
    red[t] = d0 * d0 + d1 * d1 + d2 * d2;
    __syncthreads();
    for (int s = 128; s > 0; s >>= 1) {
        if (t < s) red[t] += red[t + s];
        __syncthreads();
    }
    if (t == 0) bcast = red[0] * (1.0f / DD);
    __syncthreads();
    float inv = rsqrtf(bcast + 1e-5f);

    out[row * DD + t]       = d0 * inv * gam[t]       + bet[t];
    out[row * DD + t + 256] = d1 * inv * gam[t + 256] + bet[t + 256];
    out[row * DD + t + 512] = d2 * inv * gam[t + 512] + bet[t + 512];
}

// ---------------- launch --------------------------------------------------------
extern "C" void kernel_launch(void* const* d_in, const int* in_sizes, int n_in,
                              void* d_out, int out_size) {
    const float* queries = (const float*)d_in[0];
    const float* keys    = (const float*)d_in[1];
    const float* values  = (const float*)d_in[2];
    const int*   mask_1  = (const int*)  d_in[3];
    const int*   mask_2  = (const int*)  d_in[4];
    const float* Wq      = (const float*)d_in[5];
    const float* Wk      = (const float*)d_in[6];
    const float* Wv      = (const float*)d_in[7];
    const float* Wo      = (const float*)d_in[8];
    const float* d1_w    = (const float*)d_in[9];
    const float* d1_b    = (const float*)d_in[10];
    const float* d2_w    = (const float*)d_in[11];
    const float* d2_b    = (const float*)d_in[12];
    const float* ln_g    = (const float*)d_in[13];
    const float* ln_b    = (const float*)d_in[14];
    float* out = (float*)d_out;

    float *Qd, *Kd, *Vd, *Sd, *Ad, *Md, *H1, *Xd;
    cudaGetSymbolAddress((void**)&Qd, g_Q);
    cudaGetSymbolAddress((void**)&Kd, g_K);
    cudaGetSymbolAddress((void**)&Vd, g_V);
    cudaGetSymbolAddress((void**)&Sd, g_S);
    cudaGetSymbolAddress((void**)&Ad, g_attn);
    cudaGetSymbolAddress((void**)&Md, g_mha);
    cudaGetSymbolAddress((void**)&H1, g_h1);
    cudaGetSymbolAddress((void**)&Xd, g_x);

    const int M = NB * LL;           // 8192
    dim3 gProj(DD / 128, M / 128);   // (6, 64)

    count_masks_kernel<<<dim3(NB, 2), 256>>>(mask_1, mask_2);

    sgemm_nn_kernel<<<gProj, 256>>>(queries, Wq, nullptr, nullptr, Qd, M, DD, DD, 0);
    sgemm_nn_kernel<<<gProj, 256>>>(keys,    Wk, nullptr, nullptr, Kd, M, DD, DD, 0);
    sgemm_nn_kernel<<<gProj, 256>>>(values,  Wv, nullptr, nullptr, Vd, M, DD, DD, 0);

    scores_kernel<<<dim3(LL / 128, LL / 128, NB * NH), 256>>>(Qd, Kd, Sd);
    softmax_kernel<<<NB * NH * LL, 256>>>(Sd);
    pv_kernel<<<dim3(1, LL / 128, NB * NH), 256>>>(Sd, Vd, Ad);

    sgemm_nn_kernel<<<gProj, 256>>>(Ad, Wo,   nullptr, nullptr, Md, M, DD, DD, 0);
    sgemm_nn_kernel<<<gProj, 256>>>(Md, d1_w, d1_b,    nullptr, H1, M, DD, DD, 1 | 2);
    sgemm_nn_kernel<<<gProj, 256>>>(H1, d2_w, d2_b,    Md,      Xd, M, DD, DD, 1 | 4);

    ln_kernel<<<M, 256>>>(Xd, ln_g, ln_b, out);
}

// round 6
// speedup vs baseline: 1.4773x; 1.4773x over previous
#include <cuda_runtime.h>
#include <cuda_bf16.h>
#include <math.h>
#include <stdint.h>

#define DD   768
#define NH   12
#define HD   64
#define NB   8
#define LL   1024
#define NEGV (-1000000.0f)

// ---------------- scratch (device globals; no cudaMalloc allowed) -------------
__device__ float g_Q[NB * LL * DD];
__device__ float g_K[NB * LL * DD];
__device__ float g_V[NB * LL * DD];
__device__ float g_S[(size_t)NB * NH * LL * LL];   // 402 MB scores/attn
__device__ float g_attn[NB * LL * DD];
__device__ float g_mha[NB * LL * DD];
__device__ float g_h1[NB * LL * DD];
__device__ float g_x[NB * LL * DD];
__device__ int   g_vl[2][NB];
// bf16 split scratch (reused sequentially across all 6 GEMMs)
__device__ __nv_bfloat16 g_ah[NB * LL * DD];
__device__ __nv_bfloat16 g_al[NB * LL * DD];
__device__ __nv_bfloat16 g_bh[DD * DD];
__device__ __nv_bfloat16 g_bl[DD * DD];

// ======================= arch-generic PTX helpers ==============================
__device__ __forceinline__ uint32_t smem_to_u32(const void* p) {
    uint32_t a;
    asm("{ .reg .u64 t; cvta.to.shared.u64 t, %1; cvt.u32.u64 %0, t; }"
        : "=r"(a) : "l"(p));
    return a;
}
#define CP_ASYNC16(dst, src) \
    asm volatile("cp.async.cg.shared.global [%0], [%1], 16;" \
                 :: "r"(dst), "l"(src) : "memory")
#define CP_COMMIT() asm volatile("cp.async.commit_group;" ::: "memory")
#define CP_WAIT(n)  asm volatile("cp.async.wait_group %0;" :: "n"(n) : "memory")

#define LDMATRIX_X4(r, addr) \
    asm volatile("ldmatrix.sync.aligned.m8n8.x4.shared.b16 {%0, %1, %2, %3}, [%4];" \
                 : "=r"((r)[0]), "=r"((r)[1]), "=r"((r)[2]), "=r"((r)[3]) \
                 : "r"(addr))

#define MMA_BF16(c, a, b0, b1) \
    asm volatile("mma.sync.aligned.m16n8k16.row.col.f32.bf16.bf16.f32 " \
                 "{%0, %1, %2, %3}, {%4, %5, %6, %7}, {%8, %9}, {%0, %1, %2, %3};" \
                 : "+f"((c)[0]), "+f"((c)[1]), "+f"((c)[2]), "+f"((c)[3]) \
                 : "r"((a)[0]), "r"((a)[1]), "r"((a)[2]), "r"((a)[3]), \
                   "r"(b0), "r"(b1))

// ---------------- mask valid-length counts ------------------------------------
__global__ void count_masks_kernel(const int* __restrict__ m1,
                                   const int* __restrict__ m2) {
    const int* m = (blockIdx.y == 0) ? m1 : m2;
    int b = blockIdx.x;
    int t = threadIdx.x;
    __shared__ int red[256];
    int cnt = 0;
    for (int i = t; i < LL; i += 256) cnt += (m[b * LL + i] != 0);
    red[t] = cnt;
    __syncthreads();
    for (int s = 128; s > 0; s >>= 1) {
        if (t < s) red[t] += red[t + s];
        __syncthreads();
    }
    if (t == 0) g_vl[blockIdx.y][b] = red[0];
}

// ---------------- fp32 -> bf16 hi/lo split ------------------------------------
__global__ void __launch_bounds__(256)
split_kernel(const float* __restrict__ x, __nv_bfloat16* __restrict__ hi,
             __nv_bfloat16* __restrict__ lo) {
    int i = blockIdx.x * 256 + threadIdx.x;
    float4 v = ((const float4*)x)[i];
    __nv_bfloat16 h0 = __float2bfloat16(v.x);
    __nv_bfloat16 h1 = __float2bfloat16(v.y);
    __nv_bfloat16 h2 = __float2bfloat16(v.z);
    __nv_bfloat16 h3 = __float2bfloat16(v.w);
    __nv_bfloat16 l0 = __float2bfloat16(v.x - __bfloat162float(h0));
    __nv_bfloat16 l1 = __float2bfloat16(v.y - __bfloat162float(h1));
    __nv_bfloat16 l2 = __float2bfloat16(v.z - __bfloat162float(h2));
    __nv_bfloat16 l3 = __float2bfloat16(v.w - __bfloat162float(h3));
    __nv_bfloat162 ph0; ph0.x = h0; ph0.y = h1;
    __nv_bfloat162 ph1; ph1.x = h2; ph1.y = h3;
    __nv_bfloat162 pl0; pl0.x = l0; pl0.y = l1;
    __nv_bfloat162 pl1; pl1.x = l2; pl1.y = l3;
    ((__nv_bfloat162*)hi)[i * 2]     = ph0;
    ((__nv_bfloat162*)hi)[i * 2 + 1] = ph1;
    ((__nv_bfloat162*)lo)[i * 2]     = pl0;
    ((__nv_bfloat162*)lo)[i * 2 + 1] = pl1;
}

// ---------------- weight transpose + split: bh[n][k] = bf16(W[k][n]) ----------
__global__ void __launch_bounds__(256)
wsplit_kernel(const float* __restrict__ W, __nv_bfloat16* __restrict__ bh,
              __nv_bfloat16* __restrict__ bl) {
    __shared__ float tile[32][33];
    int tx = threadIdx.x, ty = threadIdx.y;
    int k0 = blockIdx.x * 32, n0 = blockIdx.y * 32;
#pragma unroll
    for (int r = 0; r < 4; ++r)
        tile[ty + 8 * r][tx] = W[(size_t)(k0 + ty + 8 * r) * DD + n0 + tx];
    __syncthreads();
#pragma unroll
    for (int r = 0; r < 4; ++r) {
        float v = tile[tx][ty + 8 * r];
        __nv_bfloat16 h = __float2bfloat16(v);
        size_t o = (size_t)(n0 + ty + 8 * r) * DD + k0 + tx;
        bh[o] = h;
        bl[o] = __float2bfloat16(v - __bfloat162float(h));
    }
}

// ---------------- HMMA split-bf16 GEMM: C[8192,768] = A @ W --------------------
// A as (Ahi, Alo) [M x 768] bf16 row-major; W as (Bhi, Blo) [768 x 768] n-major
// K-contiguous (Bhi[n][k] = bf16(W[k][n])). Computes hi*hi + lo*hi + hi*lo over
// 72 BK=32 chunks (3 segments x 24). 128x128 CTA tile, 8 warps (2x4), 64x32
// warp tile, mma.sync m16n8k16 bf16, cp.async double buffer.
// flags: 1=+bias[col], 2=relu, 4=+resid
__global__ void __launch_bounds__(256, 2)
tc_gemm_kernel(const __nv_bfloat16* __restrict__ Ahi, const __nv_bfloat16* __restrict__ Alo,
               const __nv_bfloat16* __restrict__ Bhi, const __nv_bfloat16* __restrict__ Blo,
               const float* __restrict__ bias, const float* __restrict__ resid,
               float* __restrict__ C, int flags) {
    // sm layout: As buf0 [0,8K), As buf1 [8K,16K), Bs buf0 [16K,24K), Bs buf1 [24K,32K)
    __shared__ __align__(128) char sm[32768];
    const int t = threadIdx.x;
    const int lane = t & 31;
    const int wid = t >> 5;
    const int wm = wid >> 2;        // 0..1
    const int wn = wid & 3;         // 0..3
    const int bm = blockIdx.y * 128;
    const int bn = blockIdx.x * 128;
    const uint32_t sbase = smem_to_u32(sm);

    float acc[4][4][4];
#pragma unroll
    for (int i = 0; i < 4; ++i)
#pragma unroll
        for (int j = 0; j < 4; ++j)
#pragma unroll
            for (int v = 0; v < 4; ++v) acc[i][j][v] = 0.0f;

    // per-thread global->smem coords: row = t/2, two 16B chunks at (t&1)*2
    const int lrow = t >> 1;
    const int lc0  = (t & 1) * 2;
    const size_t agoff = (size_t)(bm + lrow) * DD + lc0 * 8;
    const size_t bgoff = (size_t)(bn + lrow) * DD + lc0 * 8;
    uint32_t stA[2], stB[2];
#pragma unroll
    for (int j = 0; j < 2; ++j) {
        int ph = (lc0 + j) ^ ((lrow >> 1) & 3);
        stA[j] = sbase + lrow * 64 + ph * 16;
        stB[j] = sbase + 16384 + lrow * 64 + ph * 16;
    }

#define PREFETCH(it) do { \
    const int _seg = (it) / 24, _kk = ((it) % 24) * 32; \
    const __nv_bfloat16* _Ag = (_seg == 1) ? Alo : Ahi; \
    const __nv_bfloat16* _Bg = (_seg == 2) ? Blo : Bhi; \
    const uint32_t _bo = ((it) & 1) * 8192; \
    const char* _ap = (const char*)(_Ag + agoff + _kk); \
    const char* _bp = (const char*)(_Bg + bgoff + _kk); \
    CP_ASYNC16(stA[0] + _bo, _ap); \
    CP_ASYNC16(stA[1] + _bo, _ap + 16); \
    CP_ASYNC16(stB[0] + _bo, _bp); \
    CP_ASYNC16(stB[1] + _bo, _bp + 16); \
    CP_COMMIT(); \
} while (0)

    PREFETCH(0);

    for (int it = 0; it < 72; ++it) {
        const uint32_t bo = (it & 1) * 8192;
        if (it + 1 < 72) {
            PREFETCH(it + 1);
            CP_WAIT(1);
        } else {
            CP_WAIT(0);
        }
        __syncthreads();

#pragma unroll
        for (int ks = 0; ks < 2; ++ks) {
            uint32_t a[4][4];
#pragma unroll
            for (int mi = 0; mi < 4; ++mi) {
                int r = wm * 64 + mi * 16 + (lane & 15);
                int c = ks * 2 + (lane >> 4);
                uint32_t ad = sbase + bo + r * 64 + ((c ^ ((r >> 1) & 3)) * 16);
                LDMATRIX_X4(a[mi], ad);
            }
            uint32_t b[2][4];  // [ni2]{b0(ni2*2), b0(ni2*2+1), b1(ni2*2), b1(ni2*2+1)}
#pragma unroll
            for (int ni2 = 0; ni2 < 2; ++ni2) {
                int r = wn * 32 + ni2 * 16 + (lane & 15);
                int c = ks * 2 + (lane >> 4);
                uint32_t bd = sbase + 16384 + bo + r * 64 + ((c ^ ((r >> 1) & 3)) * 16);
                LDMATRIX_X4(b[ni2], bd);
            }
#pragma unroll
            for (int mi = 0; mi < 4; ++mi)
#pragma unroll
                for (int ni = 0; ni < 4; ++ni)
                    MMA_BF16(acc[mi][ni], a[mi], b[ni >> 1][ni & 1], b[ni >> 1][2 + (ni & 1)]);
        }
        __syncthreads();
    }
#undef PREFETCH

    // epilogue: acc frag (mi,ni): rows bm+wm*64+mi*16+{g, g+8}, cols bn+wn*32+ni*8+q*2
    const int g = lane >> 2, q = lane & 3;
#pragma unroll
    for (int mi = 0; mi < 4; ++mi) {
        const int r0 = bm + wm * 64 + mi * 16 + g;
#pragma unroll
        for (int ni = 0; ni < 4; ++ni) {
            const int c0 = bn + wn * 32 + ni * 8 + q * 2;
#pragma unroll
            for (int h = 0; h < 2; ++h) {
                const int r = r0 + h * 8;
                float x0 = acc[mi][ni][h * 2];
                float x1 = acc[mi][ni][h * 2 + 1];
                if (flags & 1) { x0 += bias[c0]; x1 += bias[c0 + 1]; }
                if (flags & 2) { x0 = fmaxf(x0, 0.0f); x1 = fmaxf(x1, 0.0f); }
                if (flags & 4) {
                    x0 += resid[(size_t)r * DD + c0];
                    x1 += resid[(size_t)r * DD + c0 + 1];
                }
                float2 v; v.x = x0; v.y = x1;
                *(float2*)&C[(size_t)r * DD + c0] = v;
            }
        }
    }
}

// ---------------- batched scores (fp32): S = QK^T / 8, masked -----------------
__global__ void __launch_bounds__(256)
scores_kernel(const float* __restrict__ Q, const float* __restrict__ Kk,
              float* __restrict__ S) {
    const int bh = blockIdx.z;
    const int b  = bh / NH;
    const int h  = bh % NH;
    const float* A  = Q  + (size_t)b * LL * DD + h * HD;
    const float* Bm = Kk + (size_t)b * LL * DD + h * HD;
    float* C = S + (size_t)bh * LL * LL;

    __shared__ float As[8][128];
    __shared__ float Bs[8][128];
    const int t  = threadIdx.x;
    const int bm = blockIdx.y * 128;
    const int bn = blockIdx.x * 128;
    const int tr = t >> 4;
    const int tc = t & 15;

    float acc[8][8];
#pragma unroll
    for (int i = 0; i < 8; ++i)
#pragma unroll
        for (int j = 0; j < 8; ++j) acc[i][j] = 0.0f;

    const int row = t >> 1, c4 = t & 1;

    for (int k0 = 0; k0 < HD; k0 += 8) {
        float4 va = *(const float4*)&A[(size_t)(bm + row) * DD + k0 + c4 * 4];
        As[c4 * 4 + 0][row] = va.x;
        As[c4 * 4 + 1][row] = va.y;
        As[c4 * 4 + 2][row] = va.z;
        As[c4 * 4 + 3][row] = va.w;
        float4 vb = *(const float4*)&Bm[(size_t)(bn + row) * DD + k0 + c4 * 4];
        Bs[c4 * 4 + 0][row] = vb.x;
        Bs[c4 * 4 + 1][row] = vb.y;
        Bs[c4 * 4 + 2][row] = vb.z;
        Bs[c4 * 4 + 3][row] = vb.w;
        __syncthreads();
#pragma unroll
        for (int k = 0; k < 8; ++k) {
            float a[8], bv[8];
            *(float4*)&a[0]  = *(const float4*)&As[k][tr * 8];
            *(float4*)&a[4]  = *(const float4*)&As[k][tr * 8 + 4];
            *(float4*)&bv[0] = *(const float4*)&Bs[k][tc * 8];
            *(float4*)&bv[4] = *(const float4*)&Bs[k][tc * 8 + 4];
#pragma unroll
            for (int i = 0; i < 8; ++i)
#pragma unroll
                for (int j = 0; j < 8; ++j) acc[i][j] += a[i] * bv[j];
        }
        __syncthreads();
    }

    const int vl1 = g_vl[0][b];
    const int vl2 = g_vl[1][b];
#pragma unroll
    for (int i = 0; i < 8; ++i) {
        int r = bm + tr * 8 + i;
        bool rok = r < vl2;
#pragma unroll
        for (int j = 0; j < 8; ++j) {
            int c = bn + tc * 8 + j;
            float v = acc[i][j] * 0.125f;
            C[(size_t)r * LL + c] = (rok && c < vl1) ? v : NEGV;
        }
    }
}

// ---------------- row softmax over 1024 ---------------------------------------
__global__ void __launch_bounds__(256) softmax_kernel(float* __restrict__ S) {
    const size_t row = blockIdx.x;
    float* p = S + row * LL;
    const int t = threadIdx.x;
    __shared__ float red[256];
    __shared__ float bcast;

    float4 v = *(const float4*)&p[t * 4];
    float m = fmaxf(fmaxf(v.x, v.y), fmaxf(v.z, v.w));
    red[t] = m;
    __syncthreads();
    for (int s = 128; s > 0; s >>= 1) {
        if (t < s) red[t] = fmaxf(red[t], red[t + s]);
        __syncthreads();
    }
    if (t == 0) bcast = red[0];
    __syncthreads();
    float mx = bcast;

    float4 e;
    e.x = __expf(v.x - mx);
    e.y = __expf(v.y - mx);
    e.z = __expf(v.z - mx);
    e.w = __expf(v.w - mx);
    red[t] = e.x + e.y + e.z + e.w;
    __syncthreads();
    for (int s = 128; s > 0; s >>= 1) {
        if (t < s) red[t] += red[t + s];
        __syncthreads();
    }
    if (t == 0) bcast = red[0];
    __syncthreads();
    float inv = 1.0f / bcast;

    e.x *= inv; e.y *= inv; e.z *= inv; e.w *= inv;
    *(float4*)&p[t * 4] = e;
}

// ---------------- batched PV (fp32) -------------------------------------------
__global__ void __launch_bounds__(256)
pv_kernel(const float* __restrict__ S, const float* __restrict__ V,
          float* __restrict__ O) {
    const int bh = blockIdx.z;
    const int b  = bh / NH;
    const int h  = bh % NH;
    const float* A  = S + (size_t)bh * LL * LL;
    const float* Bm = V + (size_t)b * LL * DD + h * HD;
    float* C = O + (size_t)b * LL * DD + h * HD;

    __shared__ float As[16][128];
    __shared__ float Bs[16][64];
    const int t  = threadIdx.x;
    const int bm = blockIdx.y * 128;
    const int tr = t >> 4;
    const int tc = t & 15;

    float acc[8][4];
#pragma unroll
    for (int i = 0; i < 8; ++i)
#pragma unroll
        for (int j = 0; j < 4; ++j) acc[i][j] = 0.0f;

    const int brow = t >> 4, bc4 = t & 15;

    for (int k0 = 0; k0 < LL; k0 += 16) {
#pragma unroll
        for (int g = 0; g < 2; ++g) {
            int gi  = t * 2 + g;
            int row = gi >> 2, c4 = gi & 3;
            float4 va = *(const float4*)&A[(size_t)(bm + row) * LL + k0 + c4 * 4];
            As[c4 * 4 + 0][row] = va.x;
            As[c4 * 4 + 1][row] = va.y;
            As[c4 * 4 + 2][row] = va.z;
            As[c4 * 4 + 3][row] = va.w;
        }
        float4 vb = *(const float4*)&Bm[(size_t)(k0 + brow) * DD + bc4 * 4];
        *(float4*)&Bs[brow][bc4 * 4] = vb;
        __syncthreads();
#pragma unroll
        for (int k = 0; k < 16; ++k) {
            float a[8], bv[4];
            *(float4*)&a[0]  = *(const float4*)&As[k][tr * 8];
            *(float4*)&a[4]  = *(const float4*)&As[k][tr * 8 + 4];
            *(float4*)&bv[0] = *(const float4*)&Bs[k][tc * 4];
#pragma unroll
            for (int i = 0; i < 8; ++i)
#pragma unroll
                for (int j = 0; j < 4; ++j) acc[i][j] += a[i] * bv[j];
        }
        __syncthreads();
    }

#pragma unroll
    for (int i = 0; i < 8; ++i) {
        int r = bm + tr * 8 + i;
#pragma unroll
        for (int j = 0; j < 4; ++j)
            C[(size_t)r * DD + tc * 4 + j] = acc[i][j];
    }
}

// ---------------- layernorm over D=768 ----------------------------------------
__global__ void __launch_bounds__(256)
ln_kernel(const float* __restrict__ X, const float* __restrict__ gam,
          const float* __restrict__ bet, float* __restrict__ out) {
    const size_t row = blockIdx.x;
    const float* x = X + row * DD;
    const int t = threadIdx.x;
    __shared__ float red[256];
    __shared__ float bcast;

    float v0 = x[t], v1 = x[t + 256], v2 = x[t + 512];
    red[t] = v0 + v1 + v2;
    __syncthreads();
    for (int s = 128; s > 0; s >>= 1) {
        if (t < s) red[t] += red[t + s];
        __syncthreads();
    }
    if (t == 0) bcast = red[0] * (1.0f / DD);
    __syncthreads();
    float mu = bcast;

    float d0 = v0 - mu, d1 = v1 - mu, d2 = v2 - mu;
    red[t] = d0 * d0 + d1 * d1 + d2 * d2;
    __syncthreads();
    for (int s = 128; s > 0; s >>= 1) {
        if (t < s) red[t] += red[t + s];
        __syncthreads();
    }
    if (t == 0) bcast = red[0] * (1.0f / DD);
    __syncthreads();
    float inv = rsqrtf(bcast + 1e-5f);

    out[row * DD + t]       = d0 * inv * gam[t]       + bet[t];
    out[row * DD + t + 256] = d1 * inv * gam[t + 256] + bet[t + 256];
    out[row * DD + t + 512] = d2 * inv * gam[t + 512] + bet[t + 512];
}

// ---------------- launch --------------------------------------------------------
extern "C" void kernel_launch(void* const* d_in, const int* in_sizes, int n_in,
                              void* d_out, int out_size) {
    const float* queries = (const float*)d_in[0];
    const float* keys    = (const float*)d_in[1];
    const float* values  = (const float*)d_in[2];
    const int*   mask_1  = (const int*)  d_in[3];
    const int*   mask_2  = (const int*)  d_in[4];
    const float* Wq      = (const float*)d_in[5];
    const float* Wk      = (const float*)d_in[6];
    const float* Wv      = (const float*)d_in[7];
    const float* Wo      = (const float*)d_in[8];
    const float* d1_w    = (const float*)d_in[9];
    const float* d1_b    = (const float*)d_in[10];
    const float* d2_w    = (const float*)d_in[11];
    const float* d2_b    = (const float*)d_in[12];
    const float* ln_g    = (const float*)d_in[13];
    const float* ln_b    = (const float*)d_in[14];
    float* out = (float*)d_out;

    float *Qd, *Kd, *Vd, *Sd, *Ad, *Md, *H1, *Xd;
    __nv_bfloat16 *Ah, *Al, *Bh, *Bl;
    cudaGetSymbolAddress((void**)&Qd, g_Q);
    cudaGetSymbolAddress((void**)&Kd, g_K);
    cudaGetSymbolAddress((void**)&Vd, g_V);
    cudaGetSymbolAddress((void**)&Sd, g_S);
    cudaGetSymbolAddress((void**)&Ad, g_attn);
    cudaGetSymbolAddress((void**)&Md, g_mha);
    cudaGetSymbolAddress((void**)&H1, g_h1);
    cudaGetSymbolAddress((void**)&Xd, g_x);
    cudaGetSymbolAddress((void**)&Ah, g_ah);
    cudaGetSymbolAddress((void**)&Al, g_al);
    cudaGetSymbolAddress((void**)&Bh, g_bh);
    cudaGetSymbolAddress((void**)&Bl, g_bl);

    const int M = NB * LL;                 // 8192
    const dim3 gTC(DD / 128, M / 128);     // (6, 64)
    const int nSplitBlk = (M * DD / 4) / 256;
    const dim3 gW(DD / 32, DD / 32), bW(32, 8);

    count_masks_kernel<<<dim3(NB, 2), 256>>>(mask_1, mask_2);

    // Q = queries @ Wq
    split_kernel<<<nSplitBlk, 256>>>(queries, Ah, Al);
    wsplit_kernel<<<gW, bW>>>(Wq, Bh, Bl);
    tc_gemm_kernel<<<gTC, 256>>>(Ah, Al, Bh, Bl, nullptr, nullptr, Qd, 0);
    // K = keys @ Wk
    split_kernel<<<nSplitBlk, 256>>>(keys, Ah, Al);
    wsplit_kernel<<<gW, bW>>>(Wk, Bh, Bl);
    tc_gemm_kernel<<<gTC, 256>>>(Ah, Al, Bh, Bl, nullptr, nullptr, Kd, 0);
    // V = values @ Wv
    split_kernel<<<nSplitBlk, 256>>>(values, Ah, Al);
    wsplit_kernel<<<gW, bW>>>(Wv, Bh, Bl);
    tc_gemm_kernel<<<gTC, 256>>>(Ah, Al, Bh, Bl, nullptr, nullptr, Vd, 0);

    // attention (fp32)
    scores_kernel<<<dim3(LL / 128, LL / 128, NB * NH), 256>>>(Qd, Kd, Sd);
    softmax_kernel<<<NB * NH * LL, 256>>>(Sd);
    pv_kernel<<<dim3(1, LL / 128, NB * NH), 256>>>(Sd, Vd, Ad);

    // mha = attn_out @ Wo
    split_kernel<<<nSplitBlk, 256>>>(Ad, Ah, Al);
    wsplit_kernel<<<gW, bW>>>(Wo, Bh, Bl);
    tc_gemm_kernel<<<gTC, 256>>>(Ah, Al, Bh, Bl, nullptr, nullptr, Md, 0);
    // h1 = relu(mha @ d1_w + d1_b)
    split_kernel<<<nSplitBlk, 256>>>(Md, Ah, Al);
    wsplit_kernel<<<gW, bW>>>(d1_w, Bh, Bl);
    tc_gemm_kernel<<<gTC, 256>>>(Ah, Al, Bh, Bl, d1_b, nullptr, H1, 1 | 2);
    // x = h1 @ d2_w + d2_b + mha
    split_kernel<<<nSplitBlk, 256>>>(H1, Ah, Al);
    wsplit_kernel<<<gW, bW>>>(d2_w, Bh, Bl);
    tc_gemm_kernel<<<gTC, 256>>>(Ah, Al, Bh, Bl, d2_b, Md, Xd, 1 | 4);

    ln_kernel<<<M, 256>>>(Xd, ln_g, ln_b, out);
}

// round 7
// speedup vs baseline: 2.5399x; 1.7193x over previous
#include <cuda_runtime.h>
#include <cuda_bf16.h>
#include <math.h>
#include <stdint.h>

#define DD   768
#define NH   12
#define HD   64
#define NB   8
#define LL   1024
#define NEGV (-1000000.0f)

// ---------------- scratch (device globals; no cudaMalloc allowed) -------------
__device__ __nv_bfloat16 g_qh[NB * LL * DD];
__device__ __nv_bfloat16 g_ql[NB * LL * DD];
__device__ __nv_bfloat16 g_kh[NB * LL * DD];
__device__ __nv_bfloat16 g_kl[NB * LL * DD];
__device__ __nv_bfloat16 g_vh[NB * LL * DD];
__device__ __nv_bfloat16 g_vl[NB * LL * DD];
__device__ __nv_bfloat16 g_ah[NB * LL * DD];
__device__ __nv_bfloat16 g_al[NB * LL * DD];
__device__ __nv_bfloat16 g_bh[DD * DD];
__device__ __nv_bfloat16 g_bl[DD * DD];
__device__ float g_mha[NB * LL * DD];
__device__ float g_x[NB * LL * DD];
__device__ int   g_vlen[2][NB];

// ======================= arch-generic PTX helpers ==============================
__device__ __forceinline__ uint32_t smem_to_u32(const void* p) {
    uint32_t a;
    asm("{ .reg .u64 t; cvta.to.shared.u64 t, %1; cvt.u32.u64 %0, t; }"
        : "=r"(a) : "l"(p));
    return a;
}
#define CP_ASYNC16(dst, src) \
    asm volatile("cp.async.cg.shared.global [%0], [%1], 16;" \
                 :: "r"(dst), "l"(src) : "memory")
#define CP_COMMIT() asm volatile("cp.async.commit_group;" ::: "memory")
#define CP_WAIT(n)  asm volatile("cp.async.wait_group %0;" :: "n"(n) : "memory")

#define LDMATRIX_X4(r, addr) \
    asm volatile("ldmatrix.sync.aligned.m8n8.x4.shared.b16 {%0, %1, %2, %3}, [%4];" \
                 : "=r"((r)[0]), "=r"((r)[1]), "=r"((r)[2]), "=r"((r)[3]) \
                 : "r"(addr))

#define LDMATRIX_X4_T(r, addr) \
    asm volatile("ldmatrix.sync.aligned.m8n8.x4.trans.shared.b16 {%0, %1, %2, %3}, [%4];" \
                 : "=r"((r)[0]), "=r"((r)[1]), "=r"((r)[2]), "=r"((r)[3]) \
                 : "r"(addr))

#define MMA_BF16(c, a, b0, b1) \
    asm volatile("mma.sync.aligned.m16n8k16.row.col.f32.bf16.bf16.f32 " \
                 "{%0, %1, %2, %3}, {%4, %5, %6, %7}, {%8, %9}, {%0, %1, %2, %3};" \
                 : "+f"((c)[0]), "+f"((c)[1]), "+f"((c)[2]), "+f"((c)[3]) \
                 : "r"((a)[0]), "r"((a)[1]), "r"((a)[2]), "r"((a)[3]), \
                   "r"(b0), "r"(b1))

__device__ __forceinline__ float qmax(float v) {
    v = fmaxf(v, __shfl_xor_sync(0xffffffffu, v, 1));
    v = fmaxf(v, __shfl_xor_sync(0xffffffffu, v, 2));
    return v;
}
__device__ __forceinline__ float qsum(float v) {
    v += __shfl_xor_sync(0xffffffffu, v, 1);
    v += __shfl_xor_sync(0xffffffffu, v, 2);
    return v;
}
// split pair of floats into hi/lo bf16x2 packed words
__device__ __forceinline__ void split2(float x0, float x1, uint32_t& hi, uint32_t& lo) {
    __nv_bfloat16 h0 = __float2bfloat16(x0), h1 = __float2bfloat16(x1);
    __nv_bfloat16 l0 = __float2bfloat16(x0 - __bfloat162float(h0));
    __nv_bfloat16 l1 = __float2bfloat16(x1 - __bfloat162float(h1));
    __nv_bfloat162 H; H.x = h0; H.y = h1;
    __nv_bfloat162 L; L.x = l0; L.y = l1;
    hi = *(uint32_t*)&H;
    lo = *(uint32_t*)&L;
}

// ---------------- mask valid-length counts ------------------------------------
__global__ void count_masks_kernel(const int* __restrict__ m1,
                                   const int* __restrict__ m2) {
    const int* m = (blockIdx.y == 0) ? m1 : m2;
    int b = blockIdx.x;
    int t = threadIdx.x;
    __shared__ int red[256];
    int cnt = 0;
    for (int i = t; i < LL; i += 256) cnt += (m[b * LL + i] != 0);
    red[t] = cnt;
    __syncthreads();
    for (int s = 128; s > 0; s >>= 1) {
        if (t < s) red[t] += red[t + s];
        __syncthreads();
    }
    if (t == 0) g_vlen[blockIdx.y][b] = red[0];
}

// ---------------- fp32 -> bf16 hi/lo split ------------------------------------
__global__ void __launch_bounds__(256)
split_kernel(const float* __restrict__ x, __nv_bfloat16* __restrict__ hi,
             __nv_bfloat16* __restrict__ lo) {
    int i = blockIdx.x * 256 + threadIdx.x;
    float4 v = ((const float4*)x)[i];
    uint32_t h0, l0, h1, l1;
    split2(v.x, v.y, h0, l0);
    split2(v.z, v.w, h1, l1);
    ((uint32_t*)hi)[i * 2]     = h0;
    ((uint32_t*)hi)[i * 2 + 1] = h1;
    ((uint32_t*)lo)[i * 2]     = l0;
    ((uint32_t*)lo)[i * 2 + 1] = l1;
}

// ---------------- weight transpose + split: bh[n][k] = bf16(W[k][n]) ----------
__global__ void __launch_bounds__(256)
wsplit_kernel(const float* __restrict__ W, __nv_bfloat16* __restrict__ bh,
              __nv_bfloat16* __restrict__ bl) {
    __shared__ float tile[32][33];
    int tx = threadIdx.x, ty = threadIdx.y;
    int k0 = blockIdx.x * 32, n0 = blockIdx.y * 32;
#pragma unroll
    for (int r = 0; r < 4; ++r)
        tile[ty + 8 * r][tx] = W[(size_t)(k0 + ty + 8 * r) * DD + n0 + tx];
    __syncthreads();
#pragma unroll
    for (int r = 0; r < 4; ++r) {
        float v = tile[tx][ty + 8 * r];
        __nv_bfloat16 h = __float2bfloat16(v);
        size_t o = (size_t)(n0 + ty + 8 * r) * DD + k0 + tx;
        bh[o] = h;
        bl[o] = __float2bfloat16(v - __bfloat162float(h));
    }
}

// ---------------- HMMA split-bf16 GEMM: C[8192,768] = A @ W --------------------
// flags: 1=+bias[col], 2=relu, 4=+resid. If outHi!=null, also writes scaled
// hi/lo bf16 split of the (post-flag) result. If C==null, fp32 store skipped.
__global__ void __launch_bounds__(256, 2)
tc_gemm_kernel(const __nv_bfloat16* __restrict__ Ahi, const __nv_bfloat16* __restrict__ Alo,
               const __nv_bfloat16* __restrict__ Bhi, const __nv_bfloat16* __restrict__ Blo,
               const float* __restrict__ bias, const float* __restrict__ resid,
               float* __restrict__ C,
               __nv_bfloat16* __restrict__ outHi, __nv_bfloat16* __restrict__ outLo,
               float scale, int flags) {
    __shared__ __align__(128) char sm[32768];
    const int t = threadIdx.x;
    const int lane = t & 31;
    const int wid = t >> 5;
    const int wm = wid >> 2;
    const int wn = wid & 3;
    const int bm = blockIdx.y * 128;
    const int bn = blockIdx.x * 128;
    const uint32_t sbase = smem_to_u32(sm);

    float acc[4][4][4];
#pragma unroll
    for (int i = 0; i < 4; ++i)
#pragma unroll
        for (int j = 0; j < 4; ++j)
#pragma unroll
            for (int v = 0; v < 4; ++v) acc[i][j][v] = 0.0f;

    const int lrow = t >> 1;
    const int lc0  = (t & 1) * 2;
    const size_t agoff = (size_t)(bm + lrow) * DD + lc0 * 8;
    const size_t bgoff = (size_t)(bn + lrow) * DD + lc0 * 8;
    uint32_t stA[2], stB[2];
#pragma unroll
    for (int j = 0; j < 2; ++j) {
        int ph = (lc0 + j) ^ ((lrow >> 1) & 3);
        stA[j] = sbase + lrow * 64 + ph * 16;
        stB[j] = sbase + 16384 + lrow * 64 + ph * 16;
    }

#define PREFETCH(it) do { \
    const int _seg = (it) / 24, _kk = ((it) % 24) * 32; \
    const __nv_bfloat16* _Ag = (_seg == 1) ? Alo : Ahi; \
    const __nv_bfloat16* _Bg = (_seg == 2) ? Blo : Bhi; \
    const uint32_t _bo = ((it) & 1) * 8192; \
    const char* _ap = (const char*)(_Ag + agoff + _kk); \
    const char* _bp = (const char*)(_Bg + bgoff + _kk); \
    CP_ASYNC16(stA[0] + _bo, _ap); \
    CP_ASYNC16(stA[1] + _bo, _ap + 16); \
    CP_ASYNC16(stB[0] + _bo, _bp); \
    CP_ASYNC16(stB[1] + _bo, _bp + 16); \
    CP_COMMIT(); \
} while (0)

    PREFETCH(0);

    for (int it = 0; it < 72; ++it) {
        const uint32_t bo = (it & 1) * 8192;
        if (it + 1 < 72) {
            PREFETCH(it + 1);
            CP_WAIT(1);
        } else {
            CP_WAIT(0);
        }
        __syncthreads();

#pragma unroll
        for (int ks = 0; ks < 2; ++ks) {
            uint32_t a[4][4];
#pragma unroll
            for (int mi = 0; mi < 4; ++mi) {
                int r = wm * 64 + mi * 16 + (lane & 15);
                int c = ks * 2 + (lane >> 4);
                uint32_t ad = sbase + bo + r * 64 + ((c ^ ((r >> 1) & 3)) * 16);
                LDMATRIX_X4(a[mi], ad);
            }
            uint32_t b[2][4];
#pragma unroll
            for (int ni2 = 0; ni2 < 2; ++ni2) {
                int r = wn * 32 + ni2 * 16 + (lane & 15);
                int c = ks * 2 + (lane >> 4);
                uint32_t bd = sbase + 16384 + bo + r * 64 + ((c ^ ((r >> 1) & 3)) * 16);
                LDMATRIX_X4(b[ni2], bd);
            }
#pragma unroll
            for (int mi = 0; mi < 4; ++mi)
#pragma unroll
                for (int ni = 0; ni < 4; ++ni)
                    MMA_BF16(acc[mi][ni], a[mi], b[ni >> 1][ni & 1], b[ni >> 1][2 + (ni & 1)]);
        }
        __syncthreads();
    }
#undef PREFETCH

    const int g = lane >> 2, q = lane & 3;
#pragma unroll
    for (int mi = 0; mi < 4; ++mi) {
        const int r0 = bm + wm * 64 + mi * 16 + g;
#pragma unroll
        for (int ni = 0; ni < 4; ++ni) {
            const int c0 = bn + wn * 32 + ni * 8 + q * 2;
#pragma unroll
            for (int h = 0; h < 2; ++h) {
                const int r = r0 + h * 8;
                float x0 = acc[mi][ni][h * 2];
                float x1 = acc[mi][ni][h * 2 + 1];
                if (flags & 1) { x0 += bias[c0]; x1 += bias[c0 + 1]; }
                if (flags & 2) { x0 = fmaxf(x0, 0.0f); x1 = fmaxf(x1, 0.0f); }
                if (flags & 4) {
                    x0 += resid[(size_t)r * DD + c0];
                    x1 += resid[(size_t)r * DD + c0 + 1];
                }
                if (C) {
                    float2 v; v.x = x0; v.y = x1;
                    *(float2*)&C[(size_t)r * DD + c0] = v;
                }
                if (outHi) {
                    uint32_t hw, lw;
                    split2(x0 * scale, x1 * scale, hw, lw);
                    *(uint32_t*)&outHi[(size_t)r * DD + c0] = hw;
                    *(uint32_t*)&outLo[(size_t)r * DD + c0] = lw;
                }
            }
        }
    }
}

// ---------------- fused flash attention (split bf16, HMMA) ---------------------
// grid: (LL/128, NB*NH). CTA: 256 thr, 8 warps, each warp 16 q-rows.
// Q pre-scaled by 1/8 at projection. Outputs split bf16 (Oh, Ol) for Wo GEMM.
// smem: kh[0,8K) kl[8K,16K) vh[16K,24K) vl[24K,32K); Q staged in [0,16K) first.
__global__ void __launch_bounds__(256)
flash_kernel(const __nv_bfloat16* __restrict__ Qh, const __nv_bfloat16* __restrict__ Ql,
             const __nv_bfloat16* __restrict__ Kh, const __nv_bfloat16* __restrict__ Kl,
             const __nv_bfloat16* __restrict__ Vh, const __nv_bfloat16* __restrict__ Vl,
             __nv_bfloat16* __restrict__ Oh, __nv_bfloat16* __restrict__ Ol) {
    __shared__ __align__(128) char sm[32768];
    const int t = threadIdx.x, lane = t & 31, w = t >> 5;
    const int g = lane >> 2, q = lane & 3;
    const int bm = blockIdx.x * 128;
    const int bh = blockIdx.y;
    const int b = bh / NH, h = bh % NH;
    const uint32_t sb = smem_to_u32(sm);
    const size_t hoff = (size_t)b * LL * DD + h * HD;
    const int vl1 = g_vlen[0][b], vl2 = g_vlen[1][b];

    // ---- stage Q fragments into registers ----
    uint32_t qfh[4][4], qfl[4][4];
    {
        const int lr = t >> 1, lc0 = (t & 1) * 4;
        const char* srcH = (const char*)(Qh + hoff + (size_t)(bm + lr) * DD);
#pragma unroll
        for (int j = 0; j < 4; ++j) {
            int c = lc0 + j;
            CP_ASYNC16(sb + lr * 128 + ((c ^ (lr & 7)) * 16), srcH + c * 16);
        }
        CP_COMMIT(); CP_WAIT(0);
        __syncthreads();
#pragma unroll
        for (int kb = 0; kb < 4; ++kb) {
            int r = w * 16 + (lane & 15);
            int c = kb * 2 + (lane >> 4);
            LDMATRIX_X4(qfh[kb], sb + r * 128 + ((c ^ (r & 7)) * 16));
        }
        __syncthreads();
        const char* srcL = (const char*)(Ql + hoff + (size_t)(bm + lr) * DD);
#pragma unroll
        for (int j = 0; j < 4; ++j) {
            int c = lc0 + j;
            CP_ASYNC16(sb + lr * 128 + ((c ^ (lr & 7)) * 16), srcL + c * 16);
        }
        CP_COMMIT(); CP_WAIT(0);
        __syncthreads();
#pragma unroll
        for (int kb = 0; kb < 4; ++kb) {
            int r = w * 16 + (lane & 15);
            int c = kb * 2 + (lane >> 4);
            LDMATRIX_X4(qfl[kb], sb + r * 128 + ((c ^ (r & 7)) * 16));
        }
        __syncthreads();
    }

    float o[8][4];
#pragma unroll
    for (int i = 0; i < 8; ++i)
#pragma unroll
        for (int v = 0; v < 4; ++v) o[i][v] = 0.0f;
    float m0 = -1e30f, m1 = -1e30f, l0 = 0.0f, l1 = 0.0f;

    const bool all_valid = (bm + 127) < vl2;
    int nch = 16;
    if (all_valid && vl1 > 0) {
        int c = (vl1 + 63) >> 6;
        nch = c < 16 ? c : 16;
    }
    const bool rb0 = (bm + w * 16 + g) >= vl2;
    const bool rb1 = (bm + w * 16 + g + 8) >= vl2;

    for (int ch = 0; ch < nch; ++ch) {
        const int k0 = ch * 64;
        // load K/V chunk (4 matrices, 64x64 bf16 each)
        {
            const int lr = t >> 2, lc0 = (t & 3) * 2;
            const size_t goff = hoff + (size_t)(k0 + lr) * DD;
            const char* pkh = (const char*)(Kh + goff);
            const char* pkl = (const char*)(Kl + goff);
            const char* pvh = (const char*)(Vh + goff);
            const char* pvl = (const char*)(Vl + goff);
#pragma unroll
            for (int j = 0; j < 2; ++j) {
                int c = lc0 + j;
                uint32_t so = lr * 128 + ((c ^ (lr & 7)) * 16);
                CP_ASYNC16(sb + so,          pkh + c * 16);
                CP_ASYNC16(sb + 8192 + so,   pkl + c * 16);
                CP_ASYNC16(sb + 16384 + so,  pvh + c * 16);
                CP_ASYNC16(sb + 24576 + so,  pvl + c * 16);
            }
            CP_COMMIT();
        }
        CP_WAIT(0);
        __syncthreads();

        // ---- S = Q @ K^T (3 split passes) ----
        float s[8][4];
#pragma unroll
        for (int i = 0; i < 8; ++i)
#pragma unroll
            for (int v = 0; v < 4; ++v) s[i][v] = 0.0f;

#pragma unroll
        for (int kb = 0; kb < 4; ++kb) {
            uint32_t bf[4][4];
#pragma unroll
            for (int p = 0; p < 4; ++p) {
                int r = p * 16 + (lane & 15);
                int c = kb * 2 + (lane >> 4);
                LDMATRIX_X4(bf[p], sb + r * 128 + ((c ^ (r & 7)) * 16));
            }
#pragma unroll
            for (int p = 0; p < 4; ++p) {
                MMA_BF16(s[p * 2],     qfh[kb], bf[p][0], bf[p][2]);
                MMA_BF16(s[p * 2 + 1], qfh[kb], bf[p][1], bf[p][3]);
                MMA_BF16(s[p * 2],     qfl[kb], bf[p][0], bf[p][2]);
                MMA_BF16(s[p * 2 + 1], qfl[kb], bf[p][1], bf[p][3]);
            }
#pragma unroll
            for (int p = 0; p < 4; ++p) {
                int r = p * 16 + (lane & 15);
                int c = kb * 2 + (lane >> 4);
                LDMATRIX_X4(bf[p], sb + 8192 + r * 128 + ((c ^ (r & 7)) * 16));
            }
#pragma unroll
            for (int p = 0; p < 4; ++p) {
                MMA_BF16(s[p * 2],     qfh[kb], bf[p][0], bf[p][2]);
                MMA_BF16(s[p * 2 + 1], qfh[kb], bf[p][1], bf[p][3]);
            }
        }

        // ---- masking ----
        if ((k0 + 64) > vl1 || rb0 || rb1) {
#pragma unroll
            for (int ni = 0; ni < 8; ++ni) {
#pragma unroll
                for (int v = 0; v < 4; ++v) {
                    int col = k0 + ni * 8 + q * 2 + (v & 1);
                    bool bad = (col >= vl1) || ((v < 2) ? rb0 : rb1);
                    if (bad) s[ni][v] = NEGV;
                }
            }
        }

        // ---- online softmax ----
        float cx0 = s[0][0], cx1 = s[0][2];
#pragma unroll
        for (int ni = 0; ni < 8; ++ni) {
            cx0 = fmaxf(cx0, fmaxf(s[ni][0], s[ni][1]));
            cx1 = fmaxf(cx1, fmaxf(s[ni][2], s[ni][3]));
        }
        cx0 = qmax(cx0);
        cx1 = qmax(cx1);
        float nm0 = fmaxf(m0, cx0), nm1 = fmaxf(m1, cx1);
        float sc0 = __expf(m0 - nm0), sc1 = __expf(m1 - nm1);
        m0 = nm0; m1 = nm1;
        float sum0 = 0.0f, sum1 = 0.0f;
#pragma unroll
        for (int ni = 0; ni < 8; ++ni) {
            s[ni][0] = __expf(s[ni][0] - m0);
            s[ni][1] = __expf(s[ni][1] - m0);
            s[ni][2] = __expf(s[ni][2] - m1);
            s[ni][3] = __expf(s[ni][3] - m1);
            sum0 += s[ni][0] + s[ni][1];
            sum1 += s[ni][2] + s[ni][3];
        }
        sum0 = qsum(sum0);
        sum1 = qsum(sum1);
        l0 = l0 * sc0 + sum0;
        l1 = l1 * sc1 + sum1;
#pragma unroll
        for (int nd = 0; nd < 8; ++nd) {
            o[nd][0] *= sc0; o[nd][1] *= sc0;
            o[nd][2] *= sc1; o[nd][3] *= sc1;
        }

        // ---- pack P into split bf16 A fragments ----
        uint32_t ah[4][4], al[4][4];
#pragma unroll
        for (int kb = 0; kb < 4; ++kb) {
            split2(s[2 * kb][0],     s[2 * kb][1],     ah[kb][0], al[kb][0]);
            split2(s[2 * kb][2],     s[2 * kb][3],     ah[kb][1], al[kb][1]);
            split2(s[2 * kb + 1][0], s[2 * kb + 1][1], ah[kb][2], al[kb][2]);
            split2(s[2 * kb + 1][2], s[2 * kb + 1][3], ah[kb][3], al[kb][3]);
        }

        // ---- O += P @ V (3 split passes, V^T via trans ldmatrix) ----
#pragma unroll
        for (int kb = 0; kb < 4; ++kb) {
            uint32_t bf[4][4];
#pragma unroll
            for (int p = 0; p < 4; ++p) {
                int key = kb * 16 + (lane & 15);
                int c = 2 * p + (lane >> 4);
                LDMATRIX_X4_T(bf[p], sb + 16384 + key * 128 + ((c ^ (key & 7)) * 16));
            }
#pragma unroll
            for (int p = 0; p < 4; ++p) {
                MMA_BF16(o[2 * p],     ah[kb], bf[p][0], bf[p][1]);
                MMA_BF16(o[2 * p + 1], ah[kb], bf[p][2], bf[p][3]);
                MMA_BF16(o[2 * p],     al[kb], bf[p][0], bf[p][1]);
                MMA_BF16(o[2 * p + 1], al[kb], bf[p][2], bf[p][3]);
            }
#pragma unroll
            for (int p = 0; p < 4; ++p) {
                int key = kb * 16 + (lane & 15);
                int c = 2 * p + (lane >> 4);
                LDMATRIX_X4_T(bf[p], sb + 24576 + key * 128 + ((c ^ (key & 7)) * 16));
            }
#pragma unroll
            for (int p = 0; p < 4; ++p) {
                MMA_BF16(o[2 * p],     ah[kb], bf[p][0], bf[p][1]);
                MMA_BF16(o[2 * p + 1], ah[kb], bf[p][2], bf[p][3]);
            }
        }
        __syncthreads();
    }

    // ---- epilogue: normalize + split bf16 store ----
    const float inv0 = 1.0f / l0, inv1 = 1.0f / l1;
    const int r0 = bm + w * 16 + g, r1 = r0 + 8;
    const size_t base0 = (size_t)b * LL * DD + (size_t)r0 * DD + h * HD;
    const size_t base1 = (size_t)b * LL * DD + (size_t)r1 * DD + h * HD;
#pragma unroll
    for (int nd = 0; nd < 8; ++nd) {
        uint32_t hw, lw;
        const int co = nd * 8 + q * 2;
        split2(o[nd][0] * inv0, o[nd][1] * inv0, hw, lw);
        *(uint32_t*)&Oh[base0 + co] = hw;
        *(uint32_t*)&Ol[base0 + co] = lw;
        split2(o[nd][2] * inv1, o[nd][3] * inv1, hw, lw);
        *(uint32_t*)&Oh[base1 + co] = hw;
        *(uint32_t*)&Ol[base1 + co] = lw;
    }
}

// ---------------- layernorm over D=768 ----------------------------------------
__global__ void __launch_bounds__(256)
ln_kernel(const float* __restrict__ X, const float* __restrict__ gam,
          const float* __restrict__ bet, float* __restrict__ out) {
    const size_t row = blockIdx.x;
    const float* x = X + row * DD;
    const int t = threadIdx.x;
    __shared__ float red[256];
    __shared__ float bcast;

    float v0 = x[t], v1 = x[t + 256], v2 = x[t + 512];
    red[t] = v0 + v1 + v2;
    __syncthreads();
    for (int s = 128; s > 0; s >>= 1) {
        if (t < s) red[t] += red[t + s];
        __syncthreads();
    }
    if (t == 0) bcast = red[0] * (1.0f / DD);
    __syncthreads();
    float mu = bcast;

    float d0 = v0 - mu, d1 = v1 - mu, d2 = v2 - mu;
    red[t] = d0 * d0 + d1 * d1 + d2 * d2;
    __syncthreads();
    for (int s = 128; s > 0; s >>= 1) {
        if (t < s) red[t] += red[t + s];
        __syncthreads();
    }
    if (t == 0) bcast = red[0] * (1.0f / DD);
    __syncthreads();
    float inv = rsqrtf(bcast + 1e-5f);

    out[row * DD + t]       = d0 * inv * gam[t]       + bet[t];
    out[row * DD + t + 256] = d1 * inv * gam[t + 256] + bet[t + 256];
    out[row * DD + t + 512] = d2 * inv * gam[t + 512] + bet[t + 512];
}

// ---------------- launch --------------------------------------------------------
extern "C" void kernel_launch(void* const* d_in, const int* in_sizes, int n_in,
                              void* d_out, int out_size) {
    const float* queries = (const float*)d_in[0];
    const float* keys    = (const float*)d_in[1];
    const float* values  = (const float*)d_in[2];
    const int*   mask_1  = (const int*)  d_in[3];
    const int*   mask_2  = (const int*)  d_in[4];
    const float* Wq      = (const float*)d_in[5];
    const float* Wk      = (const float*)d_in[6];
    const float* Wv      = (const float*)d_in[7];
    const float* Wo      = (const float*)d_in[8];
    const float* d1_w    = (const float*)d_in[9];
    const float* d1_b    = (const float*)d_in[10];
    const float* d2_w    = (const float*)d_in[11];
    const float* d2_b    = (const float*)d_in[12];
    const float* ln_g    = (const float*)d_in[13];
    const float* ln_b    = (const float*)d_in[14];
    float* out = (float*)d_out;

    __nv_bfloat16 *Qh, *Ql, *Kh, *Kl, *Vh, *Vl, *Ah, *Al, *Bh, *Bl;
    float *Md, *Xd;
    cudaGetSymbolAddress((void**)&Qh, g_qh);
    cudaGetSymbolAddress((void**)&Ql, g_ql);
    cudaGetSymbolAddress((void**)&Kh, g_kh);
    cudaGetSymbolAddress((void**)&Kl, g_kl);
    cudaGetSymbolAddress((void**)&Vh, g_vh);
    cudaGetSymbolAddress((void**)&Vl, g_vl);
    cudaGetSymbolAddress((void**)&Ah, g_ah);
    cudaGetSymbolAddress((void**)&Al, g_al);
    cudaGetSymbolAddress((void**)&Bh, g_bh);
    cudaGetSymbolAddress((void**)&Bl, g_bl);
    cudaGetSymbolAddress((void**)&Md, g_mha);
    cudaGetSymbolAddress((void**)&Xd, g_x);

    const int M = NB * LL;                 // 8192
    const dim3 gTC(DD / 128, M / 128);     // (6, 64)
    const int nSplitBlk = (M * DD / 4) / 256;
    const dim3 gW(DD / 32, DD / 32), bW(32, 8);

    count_masks_kernel<<<dim3(NB, 2), 256>>>(mask_1, mask_2);

    // Q = (queries @ Wq) / 8  -> split bf16 (scale folded in)
    split_kernel<<<nSplitBlk, 256>>>(queries, Ah, Al);
    wsplit_kernel<<<gW, bW>>>(Wq, Bh, Bl);
    tc_gemm_kernel<<<gTC, 256>>>(Ah, Al, Bh, Bl, nullptr, nullptr,
                                 nullptr, Qh, Ql, 0.125f, 0);
    // K = keys @ Wk -> split bf16
    split_kernel<<<nSplitBlk, 256>>>(keys, Ah, Al);
    wsplit_kernel<<<gW, bW>>>(Wk, Bh, Bl);
    tc_gemm_kernel<<<gTC, 256>>>(Ah, Al, Bh, Bl, nullptr, nullptr,
                                 nullptr, Kh, Kl, 1.0f, 0);
    // V = values @ Wv -> split bf16
    split_kernel<<<nSplitBlk, 256>>>(values, Ah, Al);
    wsplit_kernel<<<gW, bW>>>(Wv, Bh, Bl);
    tc_gemm_kernel<<<gTC, 256>>>(Ah, Al, Bh, Bl, nullptr, nullptr,
                                 nullptr, Vh, Vl, 1.0f, 0);

    // fused attention -> split bf16 output in (Ah, Al)
    flash_kernel<<<dim3(LL / 128, NB * NH), 256>>>(Qh, Ql, Kh, Kl, Vh, Vl, Ah, Al);

    // mha = attn_out @ Wo  (fp32 for residual, split bf16 for FFN1 input)
    wsplit_kernel<<<gW, bW>>>(Wo, Bh, Bl);
    tc_gemm_kernel<<<gTC, 256>>>(Ah, Al, Bh, Bl, nullptr, nullptr,
                                 Md, Qh, Ql, 1.0f, 0);
    // h1 = relu(mha @ d1_w + d1_b) -> split bf16
    wsplit_kernel<<<gW, bW>>>(d1_w, Bh, Bl);
    tc_gemm_kernel<<<gTC, 256>>>(Qh, Ql, Bh, Bl, d1_b, nullptr,
                                 nullptr, Kh, Kl, 1.0f, 1 | 2);
    // x = h1 @ d2_w + d2_b + mha (fp32)
    wsplit_kernel<<<gW, bW>>>(d2_w, Bh, Bl);
    tc_gemm_kernel<<<gTC, 256>>>(Kh, Kl, Bh, Bl, d2_b, Md,
                                 Xd, nullptr, nullptr, 1.0f, 1 | 4);

    ln_kernel<<<M, 256>>>(Xd, ln_g, ln_b, out);
}